// round 2
// baseline (speedup 1.0000x reference)
#include <cuda_runtime.h>
#include <cstdint>

// Problem constants (shapes fixed by the reference: K=64, N=128, T=32768)
#define KU   64
#define NU   128
#define EPSV 0.01f

#define INF_F (__int_as_float(0x7F800000))

// Scratch (no allocations allowed): coefficients + flags live in device globals.
// g_c = { c0, c1, c2, c3, vsum, a }
__device__ float        g_c[6];
__device__ int          g_fast;      // 1 => all inputs non-negative => cubic path exact
__device__ unsigned int g_min_bits;  // running min of mgn, stored as float bits

// Float atomic-min via the signed-min / unsigned-max bit trick.
__device__ __forceinline__ void atomic_min_float(float val) {
    if (val >= 0.0f) {
        atomicMin((int*)&g_min_bits, __float_as_int(val));
    } else {
        atomicMax(&g_min_bits, __float_as_uint(val));
    }
}

// ---------------------------------------------------------------------------
// Kernel A: per-unit sums -> cubic coefficients; non-negativity check; init min.
// One block of 64 threads, thread k owns unit k.
// ---------------------------------------------------------------------------
__global__ void prep_kernel(const float* __restrict__ t,
                            const float* __restrict__ W,
                            const float* __restrict__ b,
                            const float* __restrict__ V,
                            const float* __restrict__ a,
                            int T, int vlen) {
    const int tid = threadIdx.x;   // 0..63
    const int k   = tid;

    float s2 = 0.f, sb = 0.f, bb = 0.f;
    bool  neg = false;

    #pragma unroll 4
    for (int n = 0; n < NU; ++n) {
        const float w  = W[k * NU + n];
        const float bv = b[k * NU + n];
        s2 = fmaf(w,  w,  s2);
        sb = fmaf(w,  bv, sb);
        bb = fmaf(bv, bv, bb);
        neg |= (w < 0.f) | (bv < 0.f);
    }
    // scan t for negativity (fast path requires t >= 0)
    for (int i = tid; i < T; i += 64) neg |= (t[i] < 0.f);

    // per-unit contribution to the global cubic
    float c3 = 0.5f * s2 * s2;
    float c2 = 1.5f * s2 * sb;
    float c1 = fmaf(sb, sb, 0.5f * bb * s2);
    float c0 = 0.5f * bb * sb;

    const unsigned neg_any = __ballot_sync(0xFFFFFFFFu, neg);
    #pragma unroll
    for (int off = 16; off; off >>= 1) {
        c3 += __shfl_down_sync(0xFFFFFFFFu, c3, off);
        c2 += __shfl_down_sync(0xFFFFFFFFu, c2, off);
        c1 += __shfl_down_sync(0xFFFFFFFFu, c1, off);
        c0 += __shfl_down_sync(0xFFFFFFFFu, c0, off);
    }

    __shared__ float    red[2][4];
    __shared__ unsigned negs[2];
    const int wid = tid >> 5, lid = tid & 31;
    if (lid == 0) {
        red[wid][0] = c0; red[wid][1] = c1;
        red[wid][2] = c2; red[wid][3] = c3;
        negs[wid] = neg_any;
    }
    __syncthreads();

    if (tid == 0) {
        float vsum = 0.f;
        for (int i = 0; i < vlen; ++i) vsum = fmaf(V[i], V[i], vsum);
        g_c[0] = red[0][0] + red[1][0];
        g_c[1] = red[0][1] + red[1][1];
        g_c[2] = red[0][2] + red[1][2];
        g_c[3] = red[0][3] + red[1][3];
        g_c[4] = vsum;
        g_c[5] = a[0];
        g_fast     = (negs[0] | negs[1]) ? 0 : 1;
        g_min_bits = 0x7F800000u;  // +inf
    }
}

// ---------------------------------------------------------------------------
// Kernel B: evaluate mgn per time point (float4 vectorized), track global min.
// Fast path: Horner cubic. Slow path (never taken on this bench, kept for
// correctness robustness): full relu network.
// ---------------------------------------------------------------------------
__global__ void mgn_kernel(const float* __restrict__ t,
                           const float* __restrict__ W,
                           const float* __restrict__ b,
                           float* __restrict__ out, int T) {
    const int i4 = blockIdx.x * blockDim.x + threadIdx.x;  // vec4 index
    const int T4 = T >> 2;

    float m = INF_F;

    if (i4 < T4) {
        const float4 tv4 = reinterpret_cast<const float4*>(t)[i4];
        const float c0  = g_c[0], c1 = g_c[1], c2 = g_c[2], c3 = g_c[3];
        const float lin = g_c[4], av = g_c[5];

        float4 o;
        if (g_fast) {
            #pragma unroll
            for (int j = 0; j < 4; ++j) {
                const float tv = (&tv4.x)[j];
                const float v  = av + fmaf(lin, tv,
                        fmaf(fmaf(fmaf(c3, tv, c2), tv, c1), tv, c0));
                (&o.x)[j] = v;
                m = fminf(m, v);
            }
        } else {
            #pragma unroll
            for (int j = 0; j < 4; ++j) {
                const float tv = (&tv4.x)[j];
                float nn = 0.f;
                for (int k = 0; k < KU; ++k) {
                    float prim = 0.f, gate = 0.f;
                    #pragma unroll 8
                    for (int n = 0; n < NU; ++n) {
                        const float w  = __ldg(&W[k * NU + n]);
                        const float bv = __ldg(&b[k * NU + n]);
                        const float z  = fmaf(w, tv, bv);
                        const float r  = fmaxf(z, 0.f);
                        prim = fmaf(r, r, prim);
                        gate = fmaf(w, r, gate);
                    }
                    nn = fmaf(0.5f * prim, gate, nn);
                }
                const float v = av + fmaf(lin, tv, nn);
                (&o.x)[j] = v;
                m = fminf(m, v);
            }
        }
        reinterpret_cast<float4*>(out)[i4] = o;
    }

    // block-wide min -> atomic
    #pragma unroll
    for (int off = 16; off; off >>= 1)
        m = fminf(m, __shfl_xor_sync(0xFFFFFFFFu, m, off));

    __shared__ float wm[8];
    const int wid = threadIdx.x >> 5, lid = threadIdx.x & 31;
    if (lid == 0) wm[wid] = m;
    __syncthreads();
    if (threadIdx.x == 0) {
        float bm = wm[0];
        const int nw = (blockDim.x + 31) >> 5;
        for (int w = 1; w < nw; ++w) bm = fminf(bm, wm[w]);
        atomic_min_float(bm);
    }
}

// ---------------------------------------------------------------------------
// Kernel C: apply the positif_phi_t shift (float4 vectorized).
// ---------------------------------------------------------------------------
__global__ void corr_kernel(float* __restrict__ out, int T) {
    const float mn   = __uint_as_float(g_min_bits);
    const float corr = (mn <= 0.f) ? (EPSV - mn) : 0.f;
    const int i4 = blockIdx.x * blockDim.x + threadIdx.x;
    if (i4 < (T >> 2)) {
        float4 v = reinterpret_cast<float4*>(out)[i4];
        v.x += corr; v.y += corr; v.z += corr; v.w += corr;
        reinterpret_cast<float4*>(out)[i4] = v;
    }
}

// ---------------------------------------------------------------------------
extern "C" void kernel_launch(void* const* d_in, const int* in_sizes, int n_in,
                              void* d_out, int out_size) {
    const float* t = (const float*)d_in[0];
    const float* W = (const float*)d_in[1];
    const float* b = (const float*)d_in[2];
    const float* V = (const float*)d_in[3];
    const float* a = (const float*)d_in[4];
    float* out = (float*)d_out;

    const int T    = in_sizes[0];
    const int vlen = in_sizes[3];

    const int threads = 256;
    const int blocks4 = ((T >> 2) + threads - 1) / threads;  // T is 32768 (mult of 4)

    prep_kernel<<<1, 64>>>(t, W, b, V, a, T, vlen);
    mgn_kernel<<<blocks4, threads>>>(t, W, b, out, T);
    corr_kernel<<<blocks4, threads>>>(out, T);
}

// round 3
// speedup vs baseline: 2.9256x; 2.9256x over previous
#include <cuda_runtime.h>
#include <cstdint>

// Shapes fixed by the reference: K=64, N=128, T=32768
#define KU   64
#define NU   128
#define EPSV 0.01f
#define INF_BITS 0x7F800000u

// Device-global state (statically initialized; the last block restores these
// invariants at the end of every call, so graph replays stay deterministic).
__device__ unsigned int g_min_bits = INF_BITS;  // running min(mgn) as float bits
__device__ unsigned int g_done     = 0;         // retired-block counter

__device__ __forceinline__ void atomic_min_float(float val) {
    if (val >= 0.0f) atomicMin((int*)&g_min_bits, __float_as_int(val));
    else             atomicMax(&g_min_bits, __float_as_uint(val));
}

// ---------------------------------------------------------------------------
// Single fused kernel. 256 threads/block, each thread evaluates one float4 of t.
// Every block redundantly derives the cubic coefficients from W,b (parallel,
// so wall cost == one block's cost). Last retiring block applies the
// positif_phi_t shift and resets global state.
// ---------------------------------------------------------------------------
__global__ void __launch_bounds__(256)
fused_mgn_kernel(const float* __restrict__ t,
                 const float* __restrict__ W,
                 const float* __restrict__ b,
                 const float* __restrict__ V,
                 const float* __restrict__ a,
                 float* __restrict__ out,
                 int T, int vlen, int nblocks) {
    __shared__ float sc0[KU], sc1[KU], sc2[KU], sc3[KU];
    __shared__ float scoef[6];   // c0,c1,c2,c3,vsum,a
    __shared__ int   sneg;       // any W or b negative?
    __shared__ float swm[8];
    __shared__ int   slast;

    const int tid = threadIdx.x;
    const int T4  = T >> 2;
    const int tail = T - (T4 << 2);

    if (tid == 0) sneg = 0;
    __syncthreads();

    // ---- Phase 1: per-unit sums -> per-k cubic contributions ----
    {
        const int k = tid >> 2, quad = tid & 3;   // 4 threads per unit k
        const float4* W4 = (const float4*)W;
        const float4* B4 = (const float4*)b;
        float s2 = 0.f, sb = 0.f, bb = 0.f;
        bool  neg = false;
        #pragma unroll
        for (int j = 0; j < 8; ++j) {             // 8 float4 = 32 floats each
            const int idx = k * (NU/4) + quad * 8 + j;
            const float4 w  = W4[idx];
            const float4 bv = B4[idx];
            #pragma unroll
            for (int c = 0; c < 4; ++c) {
                const float wv = (&w.x)[c], bvv = (&bv.x)[c];
                s2 = fmaf(wv,  wv,  s2);
                sb = fmaf(wv,  bvv, sb);
                bb = fmaf(bvv, bvv, bb);
                neg |= (wv < 0.f) | (bvv < 0.f);
            }
        }
        // reduce within the 4-thread group
        #pragma unroll
        for (int off = 2; off; off >>= 1) {
            s2 += __shfl_down_sync(0xFFFFFFFFu, s2, off, 4);
            sb += __shfl_down_sync(0xFFFFFFFFu, sb, off, 4);
            bb += __shfl_down_sync(0xFFFFFFFFu, bb, off, 4);
        }
        const unsigned nb = __ballot_sync(0xFFFFFFFFu, neg);
        if ((tid & 31) == 0 && nb) atomicOr(&sneg, 1);
        if (quad == 0) {
            sc3[k] = 0.5f * s2 * s2;
            sc2[k] = 1.5f * s2 * sb;
            sc1[k] = fmaf(sb, sb, 0.5f * bb * s2);
            sc0[k] = 0.5f * bb * sb;
        }
    }
    __syncthreads();

    // ---- Phase 2: reduce over k; vsum; a ----
    if (tid < 32) {                                // warp 0: sum 64 -> 1
        float c0 = sc0[tid] + sc0[tid + 32];
        float c1 = sc1[tid] + sc1[tid + 32];
        float c2 = sc2[tid] + sc2[tid + 32];
        float c3 = sc3[tid] + sc3[tid + 32];
        #pragma unroll
        for (int off = 16; off; off >>= 1) {
            c0 += __shfl_down_sync(0xFFFFFFFFu, c0, off);
            c1 += __shfl_down_sync(0xFFFFFFFFu, c1, off);
            c2 += __shfl_down_sync(0xFFFFFFFFu, c2, off);
            c3 += __shfl_down_sync(0xFFFFFFFFu, c3, off);
        }
        if (tid == 0) { scoef[0]=c0; scoef[1]=c1; scoef[2]=c2; scoef[3]=c3; }
    } else if (tid < 64) {                         // warp 1: vsum = sum(V*V)
        const int lid = tid - 32;
        float v = 0.f;
        for (int i = lid; i < vlen; i += 32) v = fmaf(V[i], V[i], v);
        #pragma unroll
        for (int off = 16; off; off >>= 1)
            v += __shfl_down_sync(0xFFFFFFFFu, v, off);
        if (lid == 0) scoef[4] = v;
    } else if (tid == 64) {
        scoef[5] = a[0];
    }
    __syncthreads();

    const float c0 = scoef[0], c1 = scoef[1], c2 = scoef[2], c3 = scoef[3];
    const float lin = scoef[4], av = scoef[5];
    const bool wb_nonneg = (sneg == 0);

    // ---- Phase 3: evaluate one float4 of t per thread ----
    float m = __int_as_float(INF_BITS);
    const int i4 = blockIdx.x * 256 + tid;
    if (i4 < T4) {
        const float4 tv4 = ((const float4*)t)[i4];
        float4 o;
        #pragma unroll
        for (int j = 0; j < 4; ++j) {
            const float tv = (&tv4.x)[j];
            float v;
            if (wb_nonneg && tv >= 0.f) {
                // exact: relu is identity on this element's whole z-column
                v = av + fmaf(lin, tv,
                        fmaf(fmaf(fmaf(c3, tv, c2), tv, c1), tv, c0));
            } else {
                // exact fallback: brute-force relu network for this element
                float nn = 0.f;
                for (int k = 0; k < KU; ++k) {
                    float prim = 0.f, gate = 0.f;
                    #pragma unroll 8
                    for (int n = 0; n < NU; ++n) {
                        const float wv = __ldg(&W[k * NU + n]);
                        const float bv = __ldg(&b[k * NU + n]);
                        const float z  = fmaf(wv, tv, bv);
                        const float r  = fmaxf(z, 0.f);
                        prim = fmaf(r, r, prim);
                        gate = fmaf(wv, r, gate);
                    }
                    nn = fmaf(0.5f * prim, gate, nn);
                }
                v = av + fmaf(lin, tv, nn);
            }
            (&o.x)[j] = v;
            m = fminf(m, v);
        }
        ((float4*)out)[i4] = o;
    }
    // scalar tail (T not multiple of 4) handled by block 0
    if (blockIdx.x == 0 && tid < tail) {
        const int i = (T4 << 2) + tid;
        const float tv = t[i];
        float v;
        if (wb_nonneg && tv >= 0.f) {
            v = av + fmaf(lin, tv, fmaf(fmaf(fmaf(c3, tv, c2), tv, c1), tv, c0));
        } else {
            float nn = 0.f;
            for (int k = 0; k < KU; ++k) {
                float prim = 0.f, gate = 0.f;
                for (int n = 0; n < NU; ++n) {
                    const float wv = __ldg(&W[k * NU + n]);
                    const float bv = __ldg(&b[k * NU + n]);
                    const float r  = fmaxf(fmaf(wv, tv, bv), 0.f);
                    prim = fmaf(r, r, prim);
                    gate = fmaf(wv, r, gate);
                }
                nn = fmaf(0.5f * prim, gate, nn);
            }
            v = av + fmaf(lin, tv, nn);
        }
        out[i] = v;
        m = fminf(m, v);
    }

    // ---- Phase 4: block min -> global atomic min ----
    #pragma unroll
    for (int off = 16; off; off >>= 1)
        m = fminf(m, __shfl_xor_sync(0xFFFFFFFFu, m, off));
    if ((tid & 31) == 0) swm[tid >> 5] = m;
    __syncthreads();   // also orders this block's global stores for the fence below

    if (tid == 0) {
        float bm = swm[0];
        #pragma unroll
        for (int w = 1; w < 8; ++w) bm = fminf(bm, swm[w]);
        atomic_min_float(bm);
        __threadfence();                              // publish stores + min
        const unsigned prev = atomicAdd(&g_done, 1u); // retire
        slast = (prev == (unsigned)(nblocks - 1));
    }
    __syncthreads();

    // ---- Phase 5: last block applies the positif_phi_t shift + resets state ----
    if (slast) {
        __threadfence();  // acquire: make all blocks' stores visible
        const unsigned mb = *((volatile unsigned*)&g_min_bits);
        const float mn = __uint_as_float(mb);
        const float corr = (mn <= 0.f) ? (EPSV - mn) : 0.f;
        if (corr != 0.f) {
            for (int i = tid; i < T4; i += 256) {
                float4 v = ((const float4*)out)[i];
                v.x += corr; v.y += corr; v.z += corr; v.w += corr;
                ((float4*)out)[i] = v;
            }
            for (int i = (T4 << 2) + tid; i < T; i += 256)
                out[i] += corr;
        }
        __syncthreads();
        if (tid == 0) {      // restore invariants for the next graph replay
            g_done     = 0;
            g_min_bits = INF_BITS;
        }
    }
}

// ---------------------------------------------------------------------------
extern "C" void kernel_launch(void* const* d_in, const int* in_sizes, int n_in,
                              void* d_out, int out_size) {
    const float* t = (const float*)d_in[0];
    const float* W = (const float*)d_in[1];
    const float* b = (const float*)d_in[2];
    const float* V = (const float*)d_in[3];
    const float* a = (const float*)d_in[4];
    float* out = (float*)d_out;

    const int T    = in_sizes[0];
    const int vlen = in_sizes[3];

    const int T4 = T >> 2;
    int nblocks = (T4 + 255) / 256;
    if (nblocks < 1) nblocks = 1;

    fused_mgn_kernel<<<nblocks, 256>>>(t, W, b, V, a, out, T, vlen, nblocks);
}